// round 8
// baseline (speedup 1.0000x reference)
#include <cuda_runtime.h>
#include <math.h>

// Problem constants (fixed by setup_inputs)
#define N_NODES 4096
#define IN_DIM  512
#define H_DIM   256
#define OUTD    64
#define MAXDEG  192
#define EPSV    1e-8f
#define A_SCAD  3.7f
#define PROP_STEP 4
#define NBLK    148           // <= SM count: all blocks co-resident -> grid barrier safe

static const float LAMF = (float)(1.0 / 0.9 - 1.0);   // 1/LAM_HAT - 1

// ---------------- device scratch (static, no allocation) ----------------
__device__ float g_dsq [N_NODES];
__device__ float g_rdsq[N_NODES];
__device__ int   g_cnt[N_NODES];
__device__ int   g_cols[N_NODES * MAXDEG];
__device__ float g_y   [N_NODES * MAXDEG];
__device__ float g_Fu  [N_NODES * OUTD];
__device__ float g_F0  [N_NODES * OUTD];
__device__ float g_FA  [N_NODES * OUTD];
__device__ float g_FB  [N_NODES * OUTD];
__device__ float g_H   [N_NODES * H_DIM];
__device__ unsigned g_hist0[PROP_STEP][256];
__device__ unsigned g_selh [PROP_STEP][3][512];
__device__ int      g_M;
__device__ int          g_bar_count;
__device__ volatile int g_bar_phase;

// ---------------- stream fork resources (created at load, never in capture) --
static cudaStream_t g_s2;
static cudaEvent_t  g_evFork, g_evJoin;
namespace {
struct StreamInit {
    StreamInit() {
        cudaStreamCreateWithFlags(&g_s2, cudaStreamNonBlocking);
        cudaEventCreateWithFlags(&g_evFork, cudaEventDisableTiming);
        cudaEventCreateWithFlags(&g_evJoin, cudaEventDisableTiming);
    }
};
StreamInit g_stream_init;
}

// ---------------- grid barrier (requires all blocks co-resident) ------------
__device__ __forceinline__ void grid_bar() {
    __syncthreads();
    if (threadIdx.x == 0) {
        __threadfence();
        int gen = g_bar_phase;
        if (atomicAdd(&g_bar_count, 1) == NBLK - 1) {
            g_bar_count = 0;
            __threadfence();
            g_bar_phase = gen + 1;
        } else {
            while (g_bar_phase == gen) __nanosleep(64);
        }
        __threadfence();
    }
    __syncthreads();
}

// ---------------- reset ----------------
__global__ void reset_kernel() {
    int i = threadIdx.x;
    if (i == 0) { g_M = 0; g_bar_count = 0; g_bar_phase = 0; }
    for (int j = i; j < PROP_STEP * 256; j += blockDim.x) ((unsigned*)g_hist0)[j] = 0;
    for (int j = i; j < PROP_STEP * 3 * 512; j += blockDim.x) ((unsigned*)g_selh)[j] = 0;
}

// ---------------- build padded adjacency (deterministic, column-sorted) ----
__global__ __launch_bounds__(256) void build_kernel(const float* __restrict__ A) {
    __shared__ unsigned char sbit[N_NODES];
    __shared__ int scnt[256];
    int row = blockIdx.x, tid = threadIdx.x;
    const float* Arow = A + (size_t)row * N_NODES;
    for (int i = tid; i < N_NODES; i += 256) sbit[i] = (Arow[i] != 0.0f);
    __syncthreads();
    int c0 = tid * 16;
    int cnt = 0;
#pragma unroll
    for (int c = 0; c < 16; c++) cnt += sbit[c0 + c];
    scnt[tid] = cnt;
    __syncthreads();
    for (int off = 1; off < 256; off <<= 1) {
        int v = (tid >= off) ? scnt[tid - off] : 0;
        __syncthreads();
        scnt[tid] += v;
        __syncthreads();
    }
    int base  = scnt[tid] - cnt;
    int total = scnt[255];
    int pos = base;
    for (int c = 0; c < 16; c++)
        if (sbit[c0 + c] && pos < MAXDEG) g_cols[row * MAXDEG + (pos++)] = c0 + c;
    int t = min(total, MAXDEG);
    for (int e = t + tid; e < MAXDEG; e += 256)
        g_y[row * MAXDEG + e] = __int_as_float(0x7f800000);   // +inf padding
    if (tid == 0) {
        g_cnt[row] = t;
        float d = sqrtf((float)(total + 1));      // D = deg + self-loop
        g_dsq[row]  = d;
        g_rdsq[row] = 1.0f / d;
        atomicAdd(&g_M, t);
    }
}

// ---- GEMM1: H = relu(X @ W1 + b1). 128x64 tile, 8x4 acc, single wave -------
__global__ __launch_bounds__(256) void gemm1_kernel(const float* __restrict__ A,
                                                    const float* __restrict__ B,
                                                    const float* __restrict__ bias,
                                                    float* __restrict__ C) {
    const int N = H_DIM, K = IN_DIM;
    __shared__ float As[16][128];
    __shared__ float Bs[16][64];
    int tid = threadIdx.x;
    int tx = tid & 15, ty = tid >> 4;
    int row0 = blockIdx.y * 128, col0 = blockIdx.x * 64;
    int ar = tid >> 1, ak = (tid & 1) * 8;
    int bk = tid >> 4, bc = (tid & 15) * 4;
    const float* Aptr = A + (size_t)(row0 + ar) * K + ak;
    const float* Bptr = B + (size_t)bk * N + col0 + bc;

    float acc[8][4];
#pragma unroll
    for (int i = 0; i < 8; i++)
#pragma unroll
        for (int j = 0; j < 4; j++) acc[i][j] = 0.0f;

    float4 av0 = *(const float4*)Aptr;
    float4 av1 = *(const float4*)(Aptr + 4);
    float4 bv  = *(const float4*)Bptr;

    for (int k0 = 0; k0 < K; k0 += 16) {
        As[ak + 0][ar] = av0.x; As[ak + 1][ar] = av0.y;
        As[ak + 2][ar] = av0.z; As[ak + 3][ar] = av0.w;
        As[ak + 4][ar] = av1.x; As[ak + 5][ar] = av1.y;
        As[ak + 6][ar] = av1.z; As[ak + 7][ar] = av1.w;
        *(float4*)&Bs[bk][bc] = bv;
        __syncthreads();
        if (k0 + 16 < K) {
            av0 = *(const float4*)(Aptr + k0 + 16);
            av1 = *(const float4*)(Aptr + k0 + 20);
            bv  = *(const float4*)(Bptr + (size_t)(k0 + 16) * N);
        }
#pragma unroll
        for (int kk = 0; kk < 16; kk++) {
            float4 a0 = *(float4*)&As[kk][ty * 8];
            float4 a1 = *(float4*)&As[kk][ty * 8 + 4];
            float4 b  = *(float4*)&Bs[kk][tx * 4];
            float av[8] = {a0.x, a0.y, a0.z, a0.w, a1.x, a1.y, a1.z, a1.w};
            float bvv[4] = {b.x, b.y, b.z, b.w};
#pragma unroll
            for (int i = 0; i < 8; i++)
#pragma unroll
                for (int j = 0; j < 4; j++) acc[i][j] = fmaf(av[i], bvv[j], acc[i][j]);
        }
        __syncthreads();
    }
#pragma unroll
    for (int i = 0; i < 8; i++) {
        int r = row0 + ty * 8 + i;
        float4 o;
        o.x = fmaxf(acc[i][0] + bias[col0 + tx * 4 + 0], 0.0f);
        o.y = fmaxf(acc[i][1] + bias[col0 + tx * 4 + 1], 0.0f);
        o.z = fmaxf(acc[i][2] + bias[col0 + tx * 4 + 2], 0.0f);
        o.w = fmaxf(acc[i][3] + bias[col0 + tx * 4 + 3], 0.0f);
        *(float4*)&C[(size_t)r * N + col0 + tx * 4] = o;
    }
}

// ---- GEMM2 fused: F0 = H @ W2 + b2 ; Fu = rownorm(F0/dsq). 32x64 tile ------
// 128 blocks (2x concurrency of the 64x64 version); each block owns full rows.
__global__ __launch_bounds__(256) void gemm2_fused_kernel(const float* __restrict__ A,
                                                          const float* __restrict__ B,
                                                          const float* __restrict__ bias) {
    const int N = OUTD, K = H_DIM;
    __shared__ float As[16][32];
    __shared__ float Bs[16][64];
    int tid = threadIdx.x;
    int tx = tid & 15, ty = tid >> 4;       // thread owns rows ty*2..+1, cols tx*4..+3
    int row0 = blockIdx.y * 32;
    int ar = tid >> 2, ak = (tid & 3) * 4;  // A tile: first 128 threads load
    int bk = tid >> 4, bc = (tid & 15) * 4;
    const bool loadA = (tid < 128);
    const float* Aptr = A + (size_t)(row0 + ar) * K + ak;
    const float* Bptr = B + (size_t)bk * N + bc;

    float acc[2][4];
#pragma unroll
    for (int i = 0; i < 2; i++)
#pragma unroll
        for (int j = 0; j < 4; j++) acc[i][j] = 0.0f;

    float4 av = loadA ? *(const float4*)Aptr : make_float4(0, 0, 0, 0);
    float4 bv = *(const float4*)Bptr;

    for (int k0 = 0; k0 < K; k0 += 16) {
        if (loadA) {
            As[ak + 0][ar] = av.x; As[ak + 1][ar] = av.y;
            As[ak + 2][ar] = av.z; As[ak + 3][ar] = av.w;
        }
        *(float4*)&Bs[bk][bc] = bv;
        __syncthreads();
        if (k0 + 16 < K) {
            if (loadA) av = *(const float4*)(Aptr + k0 + 16);
            bv = *(const float4*)(Bptr + (size_t)(k0 + 16) * N);
        }
#pragma unroll
        for (int kk = 0; kk < 16; kk++) {
            float a0 = As[kk][ty * 2], a1 = As[kk][ty * 2 + 1];
            float4 b = *(float4*)&Bs[kk][tx * 4];
            acc[0][0] = fmaf(a0, b.x, acc[0][0]); acc[0][1] = fmaf(a0, b.y, acc[0][1]);
            acc[0][2] = fmaf(a0, b.z, acc[0][2]); acc[0][3] = fmaf(a0, b.w, acc[0][3]);
            acc[1][0] = fmaf(a1, b.x, acc[1][0]); acc[1][1] = fmaf(a1, b.y, acc[1][1]);
            acc[1][2] = fmaf(a1, b.z, acc[1][2]); acc[1][3] = fmaf(a1, b.w, acc[1][3]);
        }
        __syncthreads();
    }
    // epilogue: store F0 + fused normalize -> Fu (row spread over 16 tx lanes)
#pragma unroll
    for (int i = 0; i < 2; i++) {
        int r = row0 + ty * 2 + i;
        float4 o;
        o.x = acc[i][0] + bias[tx * 4 + 0];
        o.y = acc[i][1] + bias[tx * 4 + 1];
        o.z = acc[i][2] + bias[tx * 4 + 2];
        o.w = acc[i][3] + bias[tx * 4 + 3];
        *(float4*)&g_F0[r * OUTD + tx * 4] = o;
        float d = g_dsq[r];
        float vx = o.x / d, vy = o.y / d, vz = o.z / d, vw = o.w / d;
        float p = vx * vx + vy * vy + vz * vz + vw * vw;
#pragma unroll
        for (int off = 8; off; off >>= 1) p += __shfl_xor_sync(0xffffffffu, p, off);
        float inv = 1.0f / fmaxf(sqrtf(p), EPSV);
        float4 fo;
        fo.x = vx * inv; fo.y = vy * inv; fo.z = vz * inv; fo.w = vw * inv;
        *(float4*)&g_Fu[r * OUTD + tx * 4] = fo;
    }
}

// ---------------- persistent iteration kernel: 1024 threads/block -----------
__global__ __launch_bounds__(1024, 1)
void mega_kernel(const float* __restrict__ lg0,
                 const float* __restrict__ rdec,
                 const float* __restrict__ ralpha,
                 float* __restrict__ out) {
    __shared__ unsigned hist[256];
    __shared__ unsigned h[512];
    __shared__ unsigned sscan[256];
    __shared__ unsigned sprefix[2];
    __shared__ int      srank[2];

    const int tid  = threadIdx.x, b = blockIdx.x;
    const int lane = tid & 31, warp = tid >> 5;
    const int myrow = warp * NBLK + b;          // balanced warp->row map, one row/warp

    const float g0 = expf(lg0[0]);
    const float rr = 1.0f / (1.0f + expf(-rdec[0]));
    const float al = 1.0f / (1.0f + expf(-ralpha[0]));
    const float lam = LAMF;

    const int M = g_M;
    double idx = 0.75 * (double)(M - 1);
    long k0l = (long)floor(idx);
    const float frac = (float)(idx - (double)k0l);
    const int R0 = (int)k0l;
    long k1l = k0l + 1; if (k1l > (long)(M - 1)) k1l = M - 1;
    const int R1 = (int)k1l;

    int   cnt = 0; float rdi = 0.0f, di = 1.0f; const int* cols = g_cols;
    if (myrow < N_NODES) {
        cnt  = g_cnt[myrow];
        rdi  = g_rdsq[myrow];
        di   = g_dsq[myrow];
        cols = g_cols + myrow * MAXDEG;
    }

    for (int k = 0; k < PROP_STEP; k++) {
        const float* Fin = (k == 0) ? g_F0 : ((k & 1) ? g_FA : g_FB);
        float* Fout = (k == PROP_STEP - 1) ? out : ((k & 1) ? g_FB : g_FA);

        // ================= Y phase: one row per warp, 8-way edge ILP =========
        if (tid < 256) hist[tid] = 0;
        __syncthreads();
        if (myrow < N_NODES) {
            float fa = g_Fu[myrow * OUTD + lane];
            float fb = g_Fu[myrow * OUTD + lane + 32];
            float* yrow = g_y + myrow * MAXDEG;
            for (int e = 0; e < cnt; e += 8) {
                int ji[8];
                float p[8];
#pragma unroll
                for (int q = 0; q < 8; q++) ji[q] = cols[min(e + q, cnt - 1)] * OUTD;
#pragma unroll
                for (int q = 0; q < 8; q++)
                    p[q] = fa * g_Fu[ji[q] + lane] + fb * g_Fu[ji[q] + lane + 32];
#pragma unroll
                for (int o = 16; o; o >>= 1)
#pragma unroll
                    for (int q = 0; q < 8; q++)
                        p[q] += __shfl_xor_sync(0xffffffffu, p[q], o);
                if (lane == 0) {
#pragma unroll
                    for (int q = 0; q < 8; q++) {
                        if (e + q < cnt) {
                            float yv = fminf(fmaxf(1.0f - p[q], 0.0f), 2.0f);
                            yrow[e + q] = yv;
                            atomicAdd(&hist[__float_as_uint(yv) >> 24], 1u);
                        }
                    }
                }
            }
        }
        __syncthreads();
        if (tid < 256 && hist[tid]) atomicAdd(&g_hist0[k][tid], hist[tid]);
        grid_bar();   // y + hist0 complete

        // ============ S phase: exact 0.75-quantile -> lamc (per-block) =======
        float lamc;
        {
            float gp = g0 * powf(rr, (float)k);
            float gd;
            if (M <= 0) {
                gd = 1.0f;
            } else {
                unsigned c = 0;
                if (tid < 256) { c = g_hist0[k][tid]; sscan[tid] = c; }
                __syncthreads();
                for (int off = 1; off < 256; off <<= 1) {
                    unsigned v = 0;
                    if (tid < 256 && tid >= off) v = sscan[tid - off];
                    __syncthreads();
                    if (tid < 256) sscan[tid] += v;
                    __syncthreads();
                }
                if (tid < 256) {
                    unsigned incl = sscan[tid], excl = incl - c;
                    if ((unsigned)R0 >= excl && (unsigned)R0 < incl) { sprefix[0] = (unsigned)tid << 24; srank[0] = R0 - (int)excl; }
                    if ((unsigned)R1 >= excl && (unsigned)R1 < incl) { sprefix[1] = (unsigned)tid << 24; srank[1] = R1 - (int)excl; }
                }
                __syncthreads();
                unsigned p0 = sprefix[0], p1 = sprefix[1];
                int r0 = srank[0], r1 = srank[1];
                __syncthreads();

                const int SH[3] = {16, 8, 0};
#pragma unroll
                for (int p = 0; p < 3; p++) {
                    int sh = SH[p];
                    unsigned hm = (sh == 16) ? 0xFF000000u : (sh == 8) ? 0xFFFF0000u : 0xFFFFFF00u;
                    if (tid < 512) h[tid] = 0;
                    __syncthreads();
                    const int T = N_NODES * MAXDEG;
                    for (int s = b * 1024 + tid; s < T; s += NBLK * 1024) {
                        unsigned u = __float_as_uint(g_y[s]);
                        unsigned bb = (u >> sh) & 0xFFu;
                        if ((u & hm) == p0) atomicAdd(&h[bb], 1u);
                        if ((u & hm) == p1) atomicAdd(&h[256 + bb], 1u);
                    }
                    __syncthreads();
                    if (tid < 512 && h[tid]) atomicAdd(&g_selh[k][p][tid], h[tid]);
                    grid_bar();
                    for (int t2 = 0; t2 < 2; t2++) {
                        unsigned cc = 0;
                        if (tid < 256) { cc = g_selh[k][p][t2 * 256 + tid]; sscan[tid] = cc; }
                        __syncthreads();
                        for (int off = 1; off < 256; off <<= 1) {
                            unsigned v = 0;
                            if (tid < 256 && tid >= off) v = sscan[tid - off];
                            __syncthreads();
                            if (tid < 256) sscan[tid] += v;
                            __syncthreads();
                        }
                        if (tid < 256) {
                            unsigned incl = sscan[tid], excl = incl - cc;
                            int r = (t2 == 0) ? r0 : r1;
                            if ((unsigned)r >= excl && (unsigned)r < incl) {
                                sprefix[t2] = ((t2 == 0) ? p0 : p1) | ((unsigned)tid << sh);
                                srank[t2] = r - (int)excl;
                            }
                        }
                        __syncthreads();
                    }
                    p0 = sprefix[0]; p1 = sprefix[1];
                    r0 = srank[0];   r1 = srank[1];
                    __syncthreads();
                }
                float v0 = __uint_as_float(p0);
                float v1 = __uint_as_float(p1);
                gd = fmaxf(v0 * (1.0f - frac) + v1 * frac, EPSV);
            }
            lamc = al * (gp / A_SCAD) + (1.0f - al) * (gd / A_SCAD);
        }

        // ======== P phase: one row per warp, 4-way edge ILP ==================
        if (myrow < N_NODES) {
            const float alim = A_SCAD * lamc;
            const float wden = (A_SCAD - 1.0f);
            const float* yrow = g_y + myrow * MAXDEG;
            float S = 0.0f;
            float a0 = 0.0f, a1 = 0.0f, a2 = 0.0f, a3 = 0.0f;   // col = lane
            float c0 = 0.0f, c1 = 0.0f, c2 = 0.0f, c3 = 0.0f;   // col = lane + 32
            int e = 0;
            for (; e + 4 <= cnt; e += 4) {
                int j0 = cols[e], j1 = cols[e + 1], j2 = cols[e + 2], j3 = cols[e + 3];
                float y0 = yrow[e], y1 = yrow[e + 1], y2 = yrow[e + 2], y3 = yrow[e + 3];
                float w0 = (y0 <= lamc) ? 1.0f : ((y0 <= alim) ? (alim - y0) / (wden * fmaxf(y0, EPSV)) : 0.0f);
                float w1 = (y1 <= lamc) ? 1.0f : ((y1 <= alim) ? (alim - y1) / (wden * fmaxf(y1, EPSV)) : 0.0f);
                float w2 = (y2 <= lamc) ? 1.0f : ((y2 <= alim) ? (alim - y2) / (wden * fmaxf(y2, EPSV)) : 0.0f);
                float w3 = (y3 <= lamc) ? 1.0f : ((y3 <= alim) ? (alim - y3) / (wden * fmaxf(y3, EPSV)) : 0.0f);
                S += (w0 + w1) + (w2 + w3);
                float sc0 = w0 * rdi * g_rdsq[j0];
                float sc1 = w1 * rdi * g_rdsq[j1];
                float sc2 = w2 * rdi * g_rdsq[j2];
                float sc3 = w3 * rdi * g_rdsq[j3];
                a0 = fmaf(sc0, Fin[j0 * OUTD + lane],      a0);
                c0 = fmaf(sc0, Fin[j0 * OUTD + lane + 32], c0);
                a1 = fmaf(sc1, Fin[j1 * OUTD + lane],      a1);
                c1 = fmaf(sc1, Fin[j1 * OUTD + lane + 32], c1);
                a2 = fmaf(sc2, Fin[j2 * OUTD + lane],      a2);
                c2 = fmaf(sc2, Fin[j2 * OUTD + lane + 32], c2);
                a3 = fmaf(sc3, Fin[j3 * OUTD + lane],      a3);
                c3 = fmaf(sc3, Fin[j3 * OUTD + lane + 32], c3);
            }
            for (; e < cnt; e++) {
                int j = cols[e];
                float y = yrow[e];
                float w = (y <= lamc) ? 1.0f : ((y <= alim) ? (alim - y) / (wden * fmaxf(y, EPSV)) : 0.0f);
                S += w;
                float sc = w * rdi * g_rdsq[j];
                a0 = fmaf(sc, Fin[j * OUTD + lane],      a0);
                c0 = fmaf(sc, Fin[j * OUTD + lane + 32], c0);
            }
            float Q = S / (float)(cnt + 1) + lam;
            float f0lo = g_F0[myrow * OUTD + lane];
            float f0hi = g_F0[myrow * OUTD + lane + 32];
            float olo = ((a0 + a1) + (a2 + a3)) / Q + lam * f0lo / Q;
            float ohi = ((c0 + c1) + (c2 + c3)) / Q + lam * f0hi / Q;
            Fout[myrow * OUTD + lane]      = olo;
            Fout[myrow * OUTD + lane + 32] = ohi;

            if (k < PROP_STEP - 1) {        // fused normalize for next iteration
                float vlo = olo / di, vhi = ohi / di;
                float s2 = vlo * vlo + vhi * vhi;
#pragma unroll
                for (int o = 16; o; o >>= 1) s2 += __shfl_xor_sync(0xffffffffu, s2, o);
                float inv = 1.0f / fmaxf(sqrtf(s2), EPSV);
                g_Fu[myrow * OUTD + lane]      = vlo * inv;
                g_Fu[myrow * OUTD + lane + 32] = vhi * inv;
            }
        }
        if (k < PROP_STEP - 1) grid_bar();   // Fout/Fu visible before next Y
    }
}

// ---------------- host launcher ---------------------------------------------
extern "C" void kernel_launch(void* const* d_in, const int* in_sizes, int n_in,
                              void* d_out, int out_size) {
    const float* A      = (const float*)d_in[0];
    const float* X      = (const float*)d_in[1];
    const float* W1     = (const float*)d_in[2];
    const float* b1     = (const float*)d_in[3];
    const float* W2     = (const float*)d_in[4];
    const float* b2     = (const float*)d_in[5];
    const float* lg0    = (const float*)d_in[6];
    const float* rdec   = (const float*)d_in[7];
    const float* ralpha = (const float*)d_in[8];
    float* out = (float*)d_out;

    float* pH;
    cudaGetSymbolAddress((void**)&pH, g_H);

    // fork: reset+build (reads A) runs concurrently with the GEMM chain (X,W)
    cudaEventRecord(g_evFork, 0);
    cudaStreamWaitEvent(g_s2, g_evFork, 0);
    reset_kernel<<<1, 1024, 0, g_s2>>>();
    build_kernel<<<N_NODES, 256, 0, g_s2>>>(A);
    cudaEventRecord(g_evJoin, g_s2);

    gemm1_kernel<<<dim3(H_DIM / 64, N_NODES / 128), 256>>>(X, W1, b1, pH);
    // gemm2's normalize epilogue needs g_dsq from build: join before gemm2
    cudaStreamWaitEvent(0, g_evJoin, 0);
    gemm2_fused_kernel<<<dim3(1, N_NODES / 32), 256>>>(pH, W2, b2);
    mega_kernel<<<NBLK, 1024>>>(lg0, rdec, ralpha, out);
}